// round 13
// baseline (speedup 1.0000x reference)
#include <cuda_runtime.h>
#include <cuda_bf16.h>
#include <math_constants.h>
#include <cstdint>

// Problem constants
#define BATCH   64
#define SEQL    256
#define EDIM    512
#define SDIM    1024
#define KDIM    1024   // 2*E
#define NCLASS  2

// GEMM tile config (bf16 mma.sync m16n8k16) — proven 106.5us config
#define BM 128
#define BN 128
#define BK 64
#define LDT 72
#define TILE_HALVES (128 * LDT)
#define TILE_BYTES  (TILE_HALVES * 2)
#define STAGE_HALVES (2 * TILE_HALVES)
#define SMEM_BYTES (2 * STAGE_HALVES * 2)    // 73728
#define NKT (KDIM / BK)

// prep sizing (float4 units)
#define N_EMB_F4 (BATCH * SEQL * EDIM / 4)   // 2,097,152
#define N_WC_F4  (SDIM * KDIM / 4)           // 262,144
#define N_SP_F4  (BATCH * SDIM / 4)          // 16,384
#define GATHER_BLOCKS 1024                   // 1024*256*8 = 2,097,152
#define WC_BLOCKS 128                        // 128*256*8 = 262,144
#define PREP_BLOCKS (GATHER_BLOCKS + WC_BLOCKS)

// Scratch (static device globals)
__device__ __nv_bfloat16 g_embs[BATCH * SEQL * EDIM];
__device__ __nv_bfloat16 g_wc[SDIM * KDIM];
__device__ float g_sentpre[BATCH * SDIM];

__device__ __forceinline__ void atomicMaxFloat(float* addr, float val) {
    if (val >= 0.0f) atomicMax(reinterpret_cast<int*>(addr), __float_as_int(val));
    else             atomicMin(reinterpret_cast<unsigned int*>(addr), __float_as_uint(val));
}

__device__ __forceinline__ void mma_bf16(float c[4], const uint32_t a[4], const uint32_t b[2]) {
    asm volatile(
        "mma.sync.aligned.m16n8k16.row.col.f32.bf16.bf16.f32 "
        "{%0,%1,%2,%3}, {%4,%5,%6,%7}, {%8,%9}, {%0,%1,%2,%3};"
        : "+f"(c[0]), "+f"(c[1]), "+f"(c[2]), "+f"(c[3])
        : "r"(a[0]), "r"(a[1]), "r"(a[2]), "r"(a[3]), "r"(b[0]), "r"(b[1]));
}

__device__ __forceinline__ void cp_async16(uint32_t saddr, const void* gptr, bool pred) {
    int sz = pred ? 16 : 0;
    asm volatile("cp.async.cg.shared.global [%0], [%1], 16, %2;"
                 :: "r"(saddr), "l"(gptr), "r"(sz));
}

__device__ __forceinline__ uint32_t pack_bf16(float lo, float hi) {
    __nv_bfloat162 p = __floats2bfloat162_rn(lo, hi);
    return *reinterpret_cast<uint32_t*>(&p);
}

// ---------------------------------------------------------------------------
// Kernel 1: fused prep, uniform role per block, explicit MLP=8 load batching.
// Blocks [0,1024): gather. Blocks [1024,1152): Wc convert + sentpre init.
// ---------------------------------------------------------------------------
__global__ __launch_bounds__(256) void prep_kernel(
    const int* __restrict__ inputs,
    const float* __restrict__ emb_table,
    const float* __restrict__ Wc)
{
    if (blockIdx.x < GATHER_BLOCKS) {
        // Each block covers 2048 consecutive float4 (16 emb rows).
        const int base = blockIdx.x * 2048 + threadIdx.x;
        int idx[8], tok[8];
#pragma unroll
        for (int q = 0; q < 8; q++) {
            idx[q] = base + q * 256;
            tok[q] = __ldg(&inputs[idx[q] >> 7]);
        }
        float4 v[8];
#pragma unroll
        for (int q = 0; q < 8; q++)
            v[q] = __ldg(reinterpret_cast<const float4*>(emb_table)
                         + (size_t)tok[q] * 128 + (idx[q] & 127));
#pragma unroll
        for (int q = 0; q < 8; q++) {
            uint2 o;
            o.x = pack_bf16(v[q].x, v[q].y);
            o.y = pack_bf16(v[q].z, v[q].w);
            reinterpret_cast<uint2*>(g_embs)[idx[q]] = o;
        }
    } else {
        const int wb = blockIdx.x - GATHER_BLOCKS;       // 0..127
        const int base = wb * 2048 + threadIdx.x;
        float4 v[8];
#pragma unroll
        for (int q = 0; q < 8; q++)
            v[q] = __ldg(reinterpret_cast<const float4*>(Wc) + base + q * 256);
#pragma unroll
        for (int q = 0; q < 8; q++) {
            uint2 o;
            o.x = pack_bf16(v[q].x, v[q].y);
            o.y = pack_bf16(v[q].z, v[q].w);
            reinterpret_cast<uint2*>(g_wc)[base + q * 256] = o;
        }
        // sentpre init: 16384 f4 over 128 blocks = 128 f4/block
        if (threadIdx.x < 128)
            reinterpret_cast<float4*>(g_sentpre)[wb * 128 + threadIdx.x] =
                make_float4(-CUDART_INF_F, -CUDART_INF_F, -CUDART_INF_F, -CUDART_INF_F);
    }
}

// ---------------------------------------------------------------------------
// Kernel 2: BF16 tensor-core conv GEMM + fused max-pool (golden version).
// ---------------------------------------------------------------------------
__global__ __launch_bounds__(128, 2) void conv_max_kernel(const float* __restrict__ bc)
{
    extern __shared__ __nv_bfloat16 sm[];

    const int b   = blockIdx.z;
    const int m0  = blockIdx.y * BM;
    const int n0  = blockIdx.x * BN;
    const int tid = threadIdx.x;
    const int lane = tid & 31;
    const int warp = tid >> 5;
    const int wm = warp >> 1;
    const int wn = warp & 1;
    const int g  = lane >> 2;
    const int t  = lane & 3;

    const __nv_bfloat16* Ag = g_embs + (size_t)b * SEQL * EDIM + (size_t)m0 * EDIM;
    const __nv_bfloat16* Bg = g_wc + (size_t)n0 * KDIM;

    const uint32_t smem_u32 = (uint32_t)__cvta_generic_to_shared(sm);

    auto load_tile = [&](int kt, int st) {
        uint32_t base = smem_u32 + (uint32_t)st * (STAGE_HALVES * 2);
#pragma unroll
        for (int i = 0; i < 16; i++) {
            int c   = tid + 128 * i;
            int row = (c & 1023) >> 3;
            int ch  = c & 7;
            uint32_t daddr = base + (c < 1024 ? 0u : (uint32_t)TILE_BYTES)
                           + (uint32_t)(row * LDT * 2 + ch * 16);
            if (c < 1024) {
                bool av = (m0 + row) < (SEQL - 1);
                cp_async16(daddr, Ag + (size_t)row * EDIM + kt * BK + ch * 8, av);
            } else {
                cp_async16(daddr, Bg + (size_t)row * KDIM + kt * BK + ch * 8, true);
            }
        }
    };

    float acc[4][8][4];
#pragma unroll
    for (int mt = 0; mt < 4; mt++)
#pragma unroll
        for (int nt = 0; nt < 8; nt++)
#pragma unroll
            for (int q = 0; q < 4; q++) acc[mt][nt][q] = 0.0f;

    load_tile(0, 0);
    asm volatile("cp.async.commit_group;");

    for (int kt = 0; kt < NKT; ++kt) {
        if (kt + 1 < NKT) {
            load_tile(kt + 1, (kt + 1) & 1);
            asm volatile("cp.async.commit_group;");
            asm volatile("cp.async.wait_group 1;");
        } else {
            asm volatile("cp.async.wait_group 0;");
        }
        __syncthreads();

        const uint32_t* Aw = reinterpret_cast<const uint32_t*>(sm + (kt & 1) * STAGE_HALVES);
        const uint32_t* Bw = Aw + TILE_HALVES / 2;

#pragma unroll
        for (int ks = 0; ks < 4; ks++) {
            const int kw = ks * 8;
            uint32_t af[4][4];
#pragma unroll
            for (int mt = 0; mt < 4; mt++) {
                const uint32_t* ap = Aw + (wm * 64 + mt * 16) * (LDT / 2) + kw;
                af[mt][0] = ap[(g    ) * (LDT / 2) + t    ];
                af[mt][1] = ap[(g + 8) * (LDT / 2) + t    ];
                af[mt][2] = ap[(g    ) * (LDT / 2) + t + 4];
                af[mt][3] = ap[(g + 8) * (LDT / 2) + t + 4];
            }
            uint32_t bf[8][2];
#pragma unroll
            for (int nt = 0; nt < 8; nt++) {
                const uint32_t* bp = Bw + (wn * 64 + nt * 8 + g) * (LDT / 2) + kw;
                bf[nt][0] = bp[t];
                bf[nt][1] = bp[t + 4];
            }
#pragma unroll
            for (int mt = 0; mt < 4; mt++)
#pragma unroll
                for (int nt = 0; nt < 8; nt++)
                    mma_bf16(acc[mt][nt], af[mt], bf[nt]);
        }
        __syncthreads();
    }

    float cmax[8][2];
#pragma unroll
    for (int nt = 0; nt < 8; nt++) { cmax[nt][0] = -CUDART_INF_F; cmax[nt][1] = -CUDART_INF_F; }

#pragma unroll
    for (int mt = 0; mt < 4; mt++) {
        int r0 = m0 + wm * 64 + mt * 16 + g;
        bool v0 = r0 < (SEQL - 1);
        bool v1 = (r0 + 8) < (SEQL - 1);
#pragma unroll
        for (int nt = 0; nt < 8; nt++) {
            if (v0) {
                cmax[nt][0] = fmaxf(cmax[nt][0], acc[mt][nt][0]);
                cmax[nt][1] = fmaxf(cmax[nt][1], acc[mt][nt][1]);
            }
            if (v1) {
                cmax[nt][0] = fmaxf(cmax[nt][0], acc[mt][nt][2]);
                cmax[nt][1] = fmaxf(cmax[nt][1], acc[mt][nt][3]);
            }
        }
    }
#pragma unroll
    for (int nt = 0; nt < 8; nt++)
#pragma unroll
        for (int j = 0; j < 2; j++) {
            float v = cmax[nt][j];
            v = fmaxf(v, __shfl_xor_sync(0xffffffffu, v, 4));
            v = fmaxf(v, __shfl_xor_sync(0xffffffffu, v, 8));
            v = fmaxf(v, __shfl_xor_sync(0xffffffffu, v, 16));
            cmax[nt][j] = v;
        }
    if (g == 0) {
#pragma unroll
        for (int nt = 0; nt < 8; nt++)
#pragma unroll
            for (int j = 0; j < 2; j++) {
                int col = n0 + wn * 64 + nt * 8 + 2 * t + j;
                atomicMaxFloat(&g_sentpre[(size_t)b * SDIM + col],
                               cmax[nt][j] + __ldg(&bc[col]));
            }
    }
}

// ---------------------------------------------------------------------------
// Kernel 3: fused classifier, 1024 threads (32 warps) per batch.
// ---------------------------------------------------------------------------
__global__ __launch_bounds__(1024) void cls_kernel(
    const float* __restrict__ W1, const float* __restrict__ b1,
    const float* __restrict__ W2, const float* __restrict__ b2,
    float* __restrict__ out)
{
    const int b = blockIdx.x;
    __shared__ float sent[SDIM];
    __shared__ float h[64];

    {
        float v = g_sentpre[(size_t)b * SDIM + threadIdx.x];
        sent[threadIdx.x] = 1.0f / (1.0f + expf(-v));
    }
    __syncthreads();

    const int warp = threadIdx.x >> 5;
    const int lane = threadIdx.x & 31;
#pragma unroll
    for (int jj = 0; jj < 2; jj++) {
        int j = warp + jj * 32;
        if (j < 50) {
            const float4* wrow = reinterpret_cast<const float4*>(W1 + (size_t)j * SDIM);
            float sum = 0.0f;
#pragma unroll
            for (int q = 0; q < 8; q++) {
                int i = lane + q * 32;
                float4 v = wrow[i];
                const float* s = &sent[i * 4];
                sum = fmaf(v.x, s[0], sum);
                sum = fmaf(v.y, s[1], sum);
                sum = fmaf(v.z, s[2], sum);
                sum = fmaf(v.w, s[3], sum);
            }
#pragma unroll
            for (int o = 16; o > 0; o >>= 1) sum += __shfl_down_sync(0xffffffffu, sum, o);
            if (lane == 0) h[j] = sum + b1[j];
        }
    }
    __syncthreads();

    if (threadIdx.x < 32) {
        float p0 = 0.0f, p1 = 0.0f;
        if (threadIdx.x < 50) {
            float hv = h[threadIdx.x];
            p0 = hv * W2[threadIdx.x];
            p1 = hv * W2[50 + threadIdx.x];
        }
        int j2 = threadIdx.x + 32;
        if (j2 < 50) {
            float hv = h[j2];
            p0 = fmaf(hv, W2[j2], p0);
            p1 = fmaf(hv, W2[50 + j2], p1);
        }
#pragma unroll
        for (int o = 16; o > 0; o >>= 1) {
            p0 += __shfl_down_sync(0xffffffffu, p0, o);
            p1 += __shfl_down_sync(0xffffffffu, p1, o);
        }
        if (threadIdx.x == 0) {
            float l0 = p0 + b2[0], l1 = p1 + b2[1];
            float m   = fmaxf(l0, l1);
            float lse = m + logf(expf(l0 - m) + expf(l1 - m));
            out[b * NCLASS + 0] = l0 - lse;
            out[b * NCLASS + 1] = l1 - lse;
        }
    }
}

// ---------------------------------------------------------------------------
// kernel_launch
// inputs order: inputs(int32), emb_table, Wc, bc, W1, b1, W2, b2
// ---------------------------------------------------------------------------
extern "C" void kernel_launch(void* const* d_in, const int* in_sizes, int n_in,
                              void* d_out, int out_size) {
    const int*   inputs = (const int*)  d_in[0];
    const float* emb    = (const float*)d_in[1];
    const float* Wc     = (const float*)d_in[2];
    const float* bc     = (const float*)d_in[3];
    const float* W1     = (const float*)d_in[4];
    const float* b1     = (const float*)d_in[5];
    const float* W2     = (const float*)d_in[6];
    const float* b2     = (const float*)d_in[7];
    float* out = (float*)d_out;

    cudaFuncSetAttribute(conv_max_kernel,
                         cudaFuncAttributeMaxDynamicSharedMemorySize, SMEM_BYTES);

    prep_kernel<<<PREP_BLOCKS, 256>>>(inputs, emb, Wc);

    dim3 grid(SDIM / BN, (SEQL + BM - 1) / BM, BATCH);   // (8, 2, 64)
    conv_max_kernel<<<grid, 128, SMEM_BYTES>>>(bc);

    cls_kernel<<<BATCH, 1024>>>(W1, b1, W2, b2, out);
}